// round 2
// baseline (speedup 1.0000x reference)
#include <cuda_runtime.h>
#include <cuda_bf16.h>
#include <cstdint>

// ---------------------------------------------------------------------------
// Problem constants
// ---------------------------------------------------------------------------
#define BATCH   32
#define SEQ     2048
#define DMODEL  256
#define HIDDEN  512
#define INNER   1024
#define ROWS    (BATCH * SEQ)        // 65536
#define NCHUNK  16
#define CLEN    (SEQ / NCHUNK)       // 128

// ---------------------------------------------------------------------------
// Scratch (single __device__ array, offsets in floats).
// Buffer lifetimes:
//   xz    : live from GEMM1 until scan pass3 (z read there)
//   xc    : live from conv until scan pass3
//   gates : live from GEMM2 until scan pass3
//   g     : live from pass3 until GEMM out-proj
//   u     : live GEMM ffn1 -> GEMM ffn2   => alias onto XZ (dead by then)
//   t     : live GEMM out-proj -> LN      => alias onto GATES (dead by then)
//   hs    : live LN1 -> end
// ---------------------------------------------------------------------------
#define OFF_XZ     ((size_t)0)
#define OFF_XC     (OFF_XZ    + (size_t)ROWS * 1024)
#define OFF_GATES  (OFF_XC    + (size_t)ROWS * 512)
#define OFF_G      (OFF_GATES + (size_t)ROWS * 1024)
#define OFF_HS     (OFF_G     + (size_t)ROWS * 512)
#define OFF_P      (OFF_HS    + (size_t)ROWS * 256)
#define OFF_S      (OFF_P     + (size_t)BATCH * NCHUNK * HIDDEN)
#define OFF_CARRY  (OFF_S     + (size_t)BATCH * NCHUNK * HIDDEN)
#define SCRATCH_FLOATS (OFF_CARRY + (size_t)BATCH * NCHUNK * HIDDEN)

// Aliased (non-overlapping lifetime) views:
#define OFF_U      OFF_XZ      // ffn hidden (ROWS*1024) reuses xz
#define OFF_T      OFF_GATES   // pre-LN temp (ROWS*256) reuses gates

__device__ float g_scratch[SCRATCH_FLOATS];

// ---------------------------------------------------------------------------
// Helpers
// ---------------------------------------------------------------------------
__device__ __forceinline__ float siluf(float v) {
    return v / (1.0f + __expf(-v));
}
__device__ __forceinline__ float sigmoidf_(float v) {
    return 1.0f / (1.0f + __expf(-v));
}

// ---------------------------------------------------------------------------
// SGEMM: C[M,N] = epilogue(A[M,K] @ W[K,N])
// BM=BN=128, BK=8, 256 threads, 8x8 per thread.
// M % 128 == 0, N % 128 == 0, K % 8 == 0 (all true for this problem).
// ---------------------------------------------------------------------------
template <bool BIAS, bool SILU, bool RESID>
__global__ __launch_bounds__(256, 2)
void sgemm_kernel(const float* __restrict__ A, const float* __restrict__ W,
                  const float* __restrict__ bias, const float* __restrict__ resid,
                  float* __restrict__ C, int M, int N, int K)
{
    __shared__ float As[8][128];
    __shared__ float Bs[8][128];

    const int bn = blockIdx.x * 128;
    const int bm = blockIdx.y * 128;
    const int tid = threadIdx.x;

    const int arow = tid >> 1;           // 0..127
    const int acol = (tid & 1) * 4;      // 0 or 4
    const int brow = tid >> 5;           // 0..7
    const int bcol = (tid & 31) * 4;     // 0..124

    const int ty = tid >> 4;             // 0..15 -> row group
    const int tx = tid & 15;             // 0..15 -> col group

    float acc[8][8];
#pragma unroll
    for (int i = 0; i < 8; i++)
#pragma unroll
        for (int j = 0; j < 8; j++) acc[i][j] = 0.0f;

    const float* Aptr = A + (size_t)(bm + arow) * K + acol;
    const float* Wptr = W + (size_t)brow * N + bn + bcol;

    for (int k0 = 0; k0 < K; k0 += 8) {
        float4 av = *(const float4*)(Aptr + k0);
        float4 bv = *(const float4*)(Wptr + (size_t)k0 * N);
        As[acol + 0][arow] = av.x;
        As[acol + 1][arow] = av.y;
        As[acol + 2][arow] = av.z;
        As[acol + 3][arow] = av.w;
        *(float4*)&Bs[brow][bcol] = bv;
        __syncthreads();

#pragma unroll
        for (int k = 0; k < 8; k++) {
            float ar[8], br[8];
            *(float4*)&ar[0] = *(const float4*)&As[k][ty * 8];
            *(float4*)&ar[4] = *(const float4*)&As[k][ty * 8 + 4];
            *(float4*)&br[0] = *(const float4*)&Bs[k][tx * 8];
            *(float4*)&br[4] = *(const float4*)&Bs[k][tx * 8 + 4];
#pragma unroll
            for (int i = 0; i < 8; i++)
#pragma unroll
                for (int j = 0; j < 8; j++)
                    acc[i][j] = fmaf(ar[i], br[j], acc[i][j]);
        }
        __syncthreads();
    }

    // Epilogue
    float bvals[8];
    if (BIAS) {
#pragma unroll
        for (int j = 0; j < 8; j++) bvals[j] = bias[bn + tx * 8 + j];
    }

#pragma unroll
    for (int i = 0; i < 8; i++) {
        const int r = bm + ty * 8 + i;
        float* crow = C + (size_t)r * N + bn + tx * 8;
        float v[8];
#pragma unroll
        for (int j = 0; j < 8; j++) v[j] = acc[i][j];
        if (BIAS) {
#pragma unroll
            for (int j = 0; j < 8; j++) v[j] += bvals[j];
        }
        if (SILU) {
#pragma unroll
            for (int j = 0; j < 8; j++) v[j] = siluf(v[j]);
        }
        if (RESID) {
            const float* rrow = resid + (size_t)r * N + bn + tx * 8;
            float4 r0 = *(const float4*)(rrow);
            float4 r1 = *(const float4*)(rrow + 4);
            v[0] += r0.x; v[1] += r0.y; v[2] += r0.z; v[3] += r0.w;
            v[4] += r1.x; v[5] += r1.y; v[6] += r1.z; v[7] += r1.w;
        }
        float4 o0 = make_float4(v[0], v[1], v[2], v[3]);
        float4 o1 = make_float4(v[4], v[5], v[6], v[7]);
        *(float4*)(crow)     = o0;
        *(float4*)(crow + 4) = o1;
    }
}

// ---------------------------------------------------------------------------
// Depthwise causal conv (k=4) + bias + SiLU.
// xh = xz[:, 0:512] (row stride 1024) -> xc [ROWS, 512]
// ---------------------------------------------------------------------------
__global__ void conv_silu_kernel(const float* __restrict__ xz,
                                 const float* __restrict__ conv_w,
                                 const float* __restrict__ conv_b,
                                 float* __restrict__ xc)
{
    const int gid = blockIdx.x * blockDim.x + threadIdx.x;
    const int c   = gid & (HIDDEN - 1);
    const int row = gid >> 9;
    if (row >= ROWS) return;
    const int t = row & (SEQ - 1);

    float w0 = conv_w[c * 4 + 0];
    float w1 = conv_w[c * 4 + 1];
    float w2 = conv_w[c * 4 + 2];
    float w3 = conv_w[c * 4 + 3];

    float acc = conv_b[c];
    // xc[t] = sum_k w[k] * xh[t + k - 3]
    if (t >= 3) acc = fmaf(w0, xz[(size_t)(row - 3) * 1024 + c], acc);
    if (t >= 2) acc = fmaf(w1, xz[(size_t)(row - 2) * 1024 + c], acc);
    if (t >= 1) acc = fmaf(w2, xz[(size_t)(row - 1) * 1024 + c], acc);
    acc = fmaf(w3, xz[(size_t)row * 1024 + c], acc);

    xc[(size_t)row * HIDDEN + c] = siluf(acc);
}

// ---------------------------------------------------------------------------
// Scan helpers: compute alpha / beta' from gates + xc + softplus(Lambda)
// ---------------------------------------------------------------------------
__device__ __forceinline__ void alpha_beta(float rec, float inp, float xcv,
                                           float spl, float& a, float& bp)
{
    float sr = sigmoidf_(rec);
    a = __expf(-spl * sr);
    float beta = sqrtf(1.0f - a * a + 1e-8f) * sigmoidf_(inp);
    bp = beta * xcv;
}

// Pass 1: per (b, chunk, c) compute P = prod(alpha), S = local scan result
__global__ void scan_pass1_kernel(const float* __restrict__ gates,
                                  const float* __restrict__ xc,
                                  const float* __restrict__ Lambda,
                                  float* __restrict__ Pbuf,
                                  float* __restrict__ Sbuf)
{
    const int gid   = blockIdx.x * blockDim.x + threadIdx.x;
    const int c     = gid & (HIDDEN - 1);
    const int chunk = (gid >> 9) & (NCHUNK - 1);
    const int b     = gid >> 13;
    if (b >= BATCH) return;

    const float spl = log1pf(__expf(Lambda[c]));
    const int row0 = b * SEQ + chunk * CLEN;

    float P = 1.0f, S = 0.0f;
#pragma unroll 4
    for (int t = 0; t < CLEN; t++) {
        const size_t row = (size_t)(row0 + t);
        float rec = gates[row * 1024 + c];
        float inp = gates[row * 1024 + 512 + c];
        float xcv = xc[row * HIDDEN + c];
        float a, bp;
        alpha_beta(rec, inp, xcv, spl, a, bp);
        P *= a;
        S = fmaf(a, S, bp);
    }
    const size_t out = (size_t)(b * NCHUNK + chunk) * HIDDEN + c;
    Pbuf[out] = P;
    Sbuf[out] = S;
}

// Pass 2: per (b, c) sequential scan over chunks -> carry (h before chunk j)
__global__ void scan_pass2_kernel(const float* __restrict__ Pbuf,
                                  const float* __restrict__ Sbuf,
                                  float* __restrict__ carry)
{
    const int gid = blockIdx.x * blockDim.x + threadIdx.x;
    const int c = gid & (HIDDEN - 1);
    const int b = gid >> 9;
    if (b >= BATCH) return;

    float h = 0.0f;
#pragma unroll
    for (int j = 0; j < NCHUNK; j++) {
        const size_t idx = (size_t)(b * NCHUNK + j) * HIDDEN + c;
        carry[idx] = h;
        h = fmaf(Pbuf[idx], h, Sbuf[idx]);
    }
}

// Pass 3: re-scan with carry, output g = silu(z) * h
__global__ void scan_pass3_kernel(const float* __restrict__ gates,
                                  const float* __restrict__ xc,
                                  const float* __restrict__ xz,
                                  const float* __restrict__ Lambda,
                                  const float* __restrict__ carry,
                                  float* __restrict__ gout)
{
    const int gid   = blockIdx.x * blockDim.x + threadIdx.x;
    const int c     = gid & (HIDDEN - 1);
    const int chunk = (gid >> 9) & (NCHUNK - 1);
    const int b     = gid >> 13;
    if (b >= BATCH) return;

    const float spl = log1pf(__expf(Lambda[c]));
    const int row0 = b * SEQ + chunk * CLEN;

    float h = carry[(size_t)(b * NCHUNK + chunk) * HIDDEN + c];
#pragma unroll 4
    for (int t = 0; t < CLEN; t++) {
        const size_t row = (size_t)(row0 + t);
        float rec = gates[row * 1024 + c];
        float inp = gates[row * 1024 + 512 + c];
        float xcv = xc[row * HIDDEN + c];
        float a, bp;
        alpha_beta(rec, inp, xcv, spl, a, bp);
        h = fmaf(a, h, bp);
        float z = xz[row * 1024 + 512 + c];
        gout[row * HIDDEN + c] = h * siluf(z);
    }
}

// ---------------------------------------------------------------------------
// LayerNorm over D=256. One warp per row, 8 elements per lane.
// ---------------------------------------------------------------------------
__global__ void ln_kernel(const float* __restrict__ in,
                          const float* __restrict__ gamma,
                          const float* __restrict__ beta,
                          float* __restrict__ out)
{
    const int warp = threadIdx.x >> 5;
    const int lane = threadIdx.x & 31;
    const int row = blockIdx.x * 8 + warp;

    const float* p = in + (size_t)row * DMODEL + lane * 8;
    float x[8];
    *(float4*)&x[0] = *(const float4*)(p);
    *(float4*)&x[4] = *(const float4*)(p + 4);

    float s = 0.0f;
#pragma unroll
    for (int i = 0; i < 8; i++) s += x[i];
#pragma unroll
    for (int o = 16; o > 0; o >>= 1) s += __shfl_xor_sync(0xFFFFFFFF, s, o);
    const float mean = s * (1.0f / DMODEL);

    float s2 = 0.0f;
#pragma unroll
    for (int i = 0; i < 8; i++) {
        float d = x[i] - mean;
        s2 = fmaf(d, d, s2);
    }
#pragma unroll
    for (int o = 16; o > 0; o >>= 1) s2 += __shfl_xor_sync(0xFFFFFFFF, s2, o);
    const float rs = rsqrtf(s2 * (1.0f / DMODEL) + 1e-12f);

    float gv[8], bv[8];
    *(float4*)&gv[0] = *(const float4*)(gamma + lane * 8);
    *(float4*)&gv[4] = *(const float4*)(gamma + lane * 8 + 4);
    *(float4*)&bv[0] = *(const float4*)(beta + lane * 8);
    *(float4*)&bv[4] = *(const float4*)(beta + lane * 8 + 4);

    float o_[8];
#pragma unroll
    for (int i = 0; i < 8; i++)
        o_[i] = fmaf((x[i] - mean) * rs, gv[i], bv[i]);

    float* q = out + (size_t)row * DMODEL + lane * 8;
    *(float4*)(q)     = *(float4*)&o_[0];
    *(float4*)(q + 4) = *(float4*)&o_[4];
}

// ---------------------------------------------------------------------------
// Launch
// ---------------------------------------------------------------------------
extern "C" void kernel_launch(void* const* d_in, const int* in_sizes, int n_in,
                              void* d_out, int out_size)
{
    const float* x      = (const float*)d_in[0];
    const float* w_in   = (const float*)d_in[1];
    const float* conv_w = (const float*)d_in[2];
    const float* conv_b = (const float*)d_in[3];
    const float* w_gts  = (const float*)d_in[4];
    const float* b_gts  = (const float*)d_in[5];
    const float* Lambda = (const float*)d_in[6];
    const float* w_out  = (const float*)d_in[7];
    const float* ln1_g  = (const float*)d_in[8];
    const float* ln1_b  = (const float*)d_in[9];
    const float* ffn_w1 = (const float*)d_in[10];
    const float* ffn_b1 = (const float*)d_in[11];
    const float* ffn_w2 = (const float*)d_in[12];
    const float* ffn_b2 = (const float*)d_in[13];
    const float* ln2_g  = (const float*)d_in[14];
    const float* ln2_b  = (const float*)d_in[15];
    float* out = (float*)d_out;

    float* scratch = nullptr;
    cudaGetSymbolAddress((void**)&scratch, g_scratch);
    float* buf_xz    = scratch + OFF_XZ;
    float* buf_xc    = scratch + OFF_XC;
    float* buf_gates = scratch + OFF_GATES;
    float* buf_g     = scratch + OFF_G;
    float* buf_hs    = scratch + OFF_HS;
    float* buf_t     = scratch + OFF_T;   // aliases gates (dead after scan)
    float* buf_u     = scratch + OFF_U;   // aliases xz (dead after scan)
    float* buf_P     = scratch + OFF_P;
    float* buf_S     = scratch + OFF_S;
    float* buf_carry = scratch + OFF_CARRY;

    const dim3 gridWide(1024 / 128, ROWS / 128);   // N=1024
    const dim3 gridNarrow(256 / 128, ROWS / 128);  // N=256

    // 1) xz = x @ w_in
    sgemm_kernel<false, false, false><<<gridWide, 256>>>(
        x, w_in, nullptr, nullptr, buf_xz, ROWS, 1024, DMODEL);

    // 2) xc = silu(conv(xh) + conv_b)
    conv_silu_kernel<<<(ROWS * HIDDEN) / 256, 256>>>(buf_xz, conv_w, conv_b, buf_xc);

    // 3) gates = xc @ w_gates + b_gates
    sgemm_kernel<true, false, false><<<gridWide, 256>>>(
        buf_xc, w_gts, b_gts, nullptr, buf_gates, ROWS, 1024, HIDDEN);

    // 4-6) chunked scan, fused alpha/beta computation; g = silu(z) * h
    scan_pass1_kernel<<<(BATCH * NCHUNK * HIDDEN) / 256, 256>>>(
        buf_gates, buf_xc, Lambda, buf_P, buf_S);
    scan_pass2_kernel<<<(BATCH * HIDDEN) / 256, 256>>>(buf_P, buf_S, buf_carry);
    scan_pass3_kernel<<<(BATCH * NCHUNK * HIDDEN) / 256, 256>>>(
        buf_gates, buf_xc, buf_xz, Lambda, buf_carry, buf_g);

    // 7) t = g @ w_out + x   (t aliases gates region — gates now dead)
    sgemm_kernel<false, false, true><<<gridNarrow, 256>>>(
        buf_g, w_out, nullptr, x, buf_t, ROWS, DMODEL, HIDDEN);

    // 8) hs = LN1(t)
    ln_kernel<<<ROWS / 8, 256>>>(buf_t, ln1_g, ln1_b, buf_hs);

    // 9) u = silu(hs @ ffn_w1 + ffn_b1)   (u aliases xz region — xz now dead)
    sgemm_kernel<true, true, false><<<gridWide, 256>>>(
        buf_hs, ffn_w1, ffn_b1, nullptr, buf_u, ROWS, INNER, DMODEL);

    // 10) t = u @ ffn_w2 + ffn_b2 + hs
    sgemm_kernel<true, false, true><<<gridNarrow, 256>>>(
        buf_u, ffn_w2, ffn_b2, buf_hs, buf_t, ROWS, DMODEL, INNER);

    // 11) out = LN2(t)
    ln_kernel<<<ROWS / 8, 256>>>(buf_t, ln2_g, ln2_b, out);
}

// round 4
// speedup vs baseline: 1.7768x; 1.7768x over previous
#include <cuda_runtime.h>
#include <cuda_bf16.h>
#include <cstdint>

// ---------------------------------------------------------------------------
// Problem constants
// ---------------------------------------------------------------------------
#define BATCH   32
#define SEQ     2048
#define DMODEL  256
#define HIDDEN  512
#define INNER   1024
#define ROWS    (BATCH * SEQ)        // 65536
#define NCHUNK  16
#define CLEN    (SEQ / NCHUNK)       // 128

// ---------------------------------------------------------------------------
// Scratch buffers
// ---------------------------------------------------------------------------
#define OFFF_XZ     ((size_t)0)                          // ROWS*1024
#define OFFF_XC     (OFFF_XZ    + (size_t)ROWS * 1024)   // ROWS*512
#define OFFF_GATES  (OFFF_XC    + (size_t)ROWS * 512)    // ROWS*1024
#define OFFF_HS     (OFFF_GATES + (size_t)ROWS * 1024)   // ROWS*256
#define OFFF_P      (OFFF_HS    + (size_t)ROWS * 256)
#define OFFF_S      (OFFF_P     + (size_t)BATCH * NCHUNK * HIDDEN)
#define OFFF_CARRY  (OFFF_S     + (size_t)BATCH * NCHUNK * HIDDEN)
#define FBUF_FLOATS (OFFF_CARRY + (size_t)BATCH * NCHUNK * HIDDEN)
#define OFFF_T      OFFF_GATES   // pre-LN temp aliases gates (dead after scan)

__device__ float g_fbuf[FBUF_FLOATS];

#define OFFB_XHI    ((size_t)0)                          // ROWS*256
#define OFFB_XLO    (OFFB_XHI  + (size_t)ROWS * 256)
#define OFFB_XCHI   (OFFB_XLO  + (size_t)ROWS * 256)     // ROWS*512
#define OFFB_XCLO   (OFFB_XCHI + (size_t)ROWS * 512)
#define OFFB_GHI    (OFFB_XCLO + (size_t)ROWS * 512)     // ROWS*512
#define OFFB_GLO    (OFFB_GHI  + (size_t)ROWS * 512)
#define OFFB_HSHI   (OFFB_GLO  + (size_t)ROWS * 512)     // ROWS*256
#define OFFB_HSLO   (OFFB_HSHI + (size_t)ROWS * 256)
#define OFFB_UHI    (OFFB_HSLO + (size_t)ROWS * 256)     // ROWS*1024
#define OFFB_ULO    (OFFB_UHI  + (size_t)ROWS * 1024)
#define OFFB_W1HI   (OFFB_ULO  + (size_t)ROWS * 1024)    // 1024*256
#define OFFB_W1LO   (OFFB_W1HI + (size_t)1024 * 256)
#define OFFB_WGHI   (OFFB_W1LO + (size_t)1024 * 256)     // 1024*512
#define OFFB_WGLO   (OFFB_WGHI + (size_t)1024 * 512)
#define OFFB_WOHI   (OFFB_WGLO + (size_t)1024 * 512)     // 256*512
#define OFFB_WOLO   (OFFB_WOHI + (size_t)256 * 512)
#define OFFB_F1HI   (OFFB_WOLO + (size_t)256 * 512)      // 1024*256
#define OFFB_F1LO   (OFFB_F1HI + (size_t)1024 * 256)
#define OFFB_F2HI   (OFFB_F1LO + (size_t)1024 * 256)     // 256*1024
#define OFFB_F2LO   (OFFB_F2HI + (size_t)256 * 1024)
#define BBUF_ELEMS  (OFFB_F2LO + (size_t)256 * 1024)

__device__ __nv_bfloat16 g_bbuf[BBUF_ELEMS];

// ---------------------------------------------------------------------------
// Small helpers
// ---------------------------------------------------------------------------
__device__ __forceinline__ float siluf(float v)     { return v / (1.0f + __expf(-v)); }
__device__ __forceinline__ float sigmoidf_(float v) { return 1.0f / (1.0f + __expf(-v)); }

__device__ __forceinline__ void split_bf16(float v, __nv_bfloat16& h, __nv_bfloat16& l) {
    h = __float2bfloat16(v);
    l = __float2bfloat16(v - __bfloat162float(h));
}

__device__ __forceinline__ uint32_t smem_u32(const void* p) {
    uint32_t a;
    asm("{ .reg .u64 t; cvta.to.shared.u64 t, %1; cvt.u32.u64 %0, t; }" : "=r"(a) : "l"(p));
    return a;
}

// cp.async (16B)
__device__ __forceinline__ void cp_async16(uint32_t dst, const void* src) {
    asm volatile("cp.async.cg.shared.global [%0], [%1], 16;" :: "r"(dst), "l"(src));
}
__device__ __forceinline__ void cp_commit() { asm volatile("cp.async.commit_group;"); }
template <int N> __device__ __forceinline__ void cp_wait() {
    asm volatile("cp.async.wait_group %0;" :: "n"(N));
}

// ldmatrix x4 (non-transposed)
__device__ __forceinline__ void ldsm4(uint32_t& r0, uint32_t& r1, uint32_t& r2,
                                      uint32_t& r3, uint32_t addr) {
    asm volatile("ldmatrix.sync.aligned.m8n8.x4.shared.b16 {%0,%1,%2,%3}, [%4];"
                 : "=r"(r0), "=r"(r1), "=r"(r2), "=r"(r3) : "r"(addr));
}

// bf16 mma, fp32 accumulate
__device__ __forceinline__ void mma_bf16(float* d, const uint32_t* a, const uint32_t* b) {
    asm volatile(
        "mma.sync.aligned.m16n8k16.row.col.f32.bf16.bf16.f32 "
        "{%0,%1,%2,%3}, {%4,%5,%6,%7}, {%8,%9}, {%0,%1,%2,%3};"
        : "+f"(d[0]), "+f"(d[1]), "+f"(d[2]), "+f"(d[3])
        : "r"(a[0]), "r"(a[1]), "r"(a[2]), "r"(a[3]), "r"(b[0]), "r"(b[1]));
}

// ---------------------------------------------------------------------------
// Tensor-core GEMM via mma.sync: C[M,N] = epi((Ahi+Alo) @ (Whi+Wlo)^T)
// A split [M,K] bf16, W split [N,K] bf16. BM=128, BN=128, BK=32, 256 threads.
// SMEM rows padded to 40 bf16 (80 B) -> conflict-free ldmatrix.
// ---------------------------------------------------------------------------
#define EPI_BIAS   1
#define EPI_SILU   2
#define EPI_RESID  4
#define EPI_SPLIT  8

#define PADB        80                      // bytes per 32-elem row in smem
#define OP_BYTES    (128 * PADB)            // 10240
#define OFF_AHI     0
#define OFF_ALO     (OP_BYTES)
#define OFF_WHI     (2 * OP_BYTES)
#define OFF_WLO     (3 * OP_BYTES)
#define STAGE_BYTES (4 * OP_BYTES)          // 40960
#define GEMM_DYN_SMEM (2 * STAGE_BYTES)     // 81920

template <int EPI>
__global__ __launch_bounds__(256, 1)
void mma_gemm(const __nv_bfloat16* __restrict__ Ahi, const __nv_bfloat16* __restrict__ Alo,
              const __nv_bfloat16* __restrict__ Whi, const __nv_bfloat16* __restrict__ Wlo,
              const float* __restrict__ bias, const float* __restrict__ resid,
              float* __restrict__ Cf, __nv_bfloat16* __restrict__ Chi,
              __nv_bfloat16* __restrict__ Clo, int N, int K)
{
    extern __shared__ char smem[];
    const uint32_t sbase = smem_u32(smem);

    const int tid  = threadIdx.x;
    const int bm   = blockIdx.y * 128;
    const int bn   = blockIdx.x * 128;
    const int KS   = K >> 5;

    const int w    = tid >> 5;
    const int lane = tid & 31;
    const int wm   = w & 3;                 // 0..3 (rows, *32)
    const int wn   = w >> 2;                // 0..1 (cols, *64)

    // loader mapping: 4 chunks of 16B per 64B row; 2 rows per thread per operand
    const int chunk = tid & 3;
    const int rh    = tid >> 2;             // 0..63

    auto load_stage = [&](int s) {
        const uint32_t sb = sbase + (s & 1) * STAGE_BYTES;
        const int k0 = s * 32;
#pragma unroll
        for (int h = 0; h < 2; h++) {
            const int row = rh + h * 64;
            const uint32_t so = (uint32_t)(row * PADB + chunk * 16);
            const size_t ga = (size_t)(bm + row) * K + k0 + chunk * 8;
            const size_t gw = (size_t)(bn + row) * K + k0 + chunk * 8;
            cp_async16(sb + OFF_AHI + so, Ahi + ga);
            cp_async16(sb + OFF_ALO + so, Alo + ga);
            cp_async16(sb + OFF_WHI + so, Whi + gw);
            cp_async16(sb + OFF_WLO + so, Wlo + gw);
        }
        cp_commit();
    };

    float acc[2][8][4];
#pragma unroll
    for (int i = 0; i < 2; i++)
#pragma unroll
        for (int j = 0; j < 8; j++)
#pragma unroll
            for (int q = 0; q < 4; q++) acc[i][j][q] = 0.0f;

    // ldmatrix lane addressing
    const int lt = lane >> 3;               // tile index 0..3
    const int lr = lane & 7;                // row within tile
    // A tiles: (row-half, col-half) = (lt&1, lt>>1)
    const uint32_t a_off = (uint32_t)(((lt & 1) * 8 + lr) * PADB + (lt >> 1) * 16);
    // B tiles: (n-half, k-half) = (lt>>1, lt&1)
    const uint32_t b_off = (uint32_t)(((lt >> 1) * 8 + lr) * PADB + (lt & 1) * 16);

    load_stage(0);

    for (int s = 0; s < KS; s++) {
        if (s + 1 < KS) load_stage(s + 1);
        if (s + 1 < KS) cp_wait<1>(); else cp_wait<0>();
        __syncthreads();

        const uint32_t sb = sbase + (s & 1) * STAGE_BYTES;
#pragma unroll
        for (int kk = 0; kk < 2; kk++) {
            const uint32_t kofs = kk * 32;  // 16 bf16 = 32 B

            uint32_t ahi[2][4], alo[2][4];
#pragma unroll
            for (int mt = 0; mt < 2; mt++) {
                const uint32_t abase = (uint32_t)((wm * 32 + mt * 16) * PADB) + kofs + a_off;
                ldsm4(ahi[mt][0], ahi[mt][1], ahi[mt][2], ahi[mt][3], sb + OFF_AHI + abase);
                ldsm4(alo[mt][0], alo[mt][1], alo[mt][2], alo[mt][3], sb + OFF_ALO + abase);
            }

            uint32_t bhi[8][2], blo[8][2];
#pragma unroll
            for (int nq = 0; nq < 4; nq++) {
                const uint32_t bbase = (uint32_t)((wn * 64 + nq * 16) * PADB) + kofs + b_off;
                uint32_t r0, r1, r2, r3;
                ldsm4(r0, r1, r2, r3, sb + OFF_WHI + bbase);
                bhi[nq * 2][0] = r0; bhi[nq * 2][1] = r1;
                bhi[nq * 2 + 1][0] = r2; bhi[nq * 2 + 1][1] = r3;
                ldsm4(r0, r1, r2, r3, sb + OFF_WLO + bbase);
                blo[nq * 2][0] = r0; blo[nq * 2][1] = r1;
                blo[nq * 2 + 1][0] = r2; blo[nq * 2 + 1][1] = r3;
            }

#pragma unroll
            for (int mt = 0; mt < 2; mt++)
#pragma unroll
                for (int nf = 0; nf < 8; nf++) {
                    mma_bf16(acc[mt][nf], ahi[mt], bhi[nf]);
                    mma_bf16(acc[mt][nf], ahi[mt], blo[nf]);
                    mma_bf16(acc[mt][nf], alo[mt], bhi[nf]);
                }
        }
        __syncthreads();
    }

    // epilogue ---------------------------------------------------------------
    const int qrow = lane >> 2;             // 0..7
    const int qcol = (lane & 3) * 2;        // 0,2,4,6

#pragma unroll
    for (int mt = 0; mt < 2; mt++) {
#pragma unroll
        for (int nf = 0; nf < 8; nf++) {
            const int r0 = bm + wm * 32 + mt * 16 + qrow;
            const int r1 = r0 + 8;
            const int c  = bn + wn * 64 + nf * 8 + qcol;

            float v00 = acc[mt][nf][0], v01 = acc[mt][nf][1];  // row r0, cols c,c+1
            float v10 = acc[mt][nf][2], v11 = acc[mt][nf][3];  // row r1

            if (EPI & EPI_BIAS) {
                const float b0 = __ldg(bias + c), b1 = __ldg(bias + c + 1);
                v00 += b0; v01 += b1; v10 += b0; v11 += b1;
            }
            if (EPI & EPI_SILU) {
                v00 = siluf(v00); v01 = siluf(v01);
                v10 = siluf(v10); v11 = siluf(v11);
            }
            const size_t o0 = (size_t)r0 * N + c;
            const size_t o1 = (size_t)r1 * N + c;
            if (EPI & EPI_RESID) {
                float2 q0 = *(const float2*)(resid + o0);
                float2 q1 = *(const float2*)(resid + o1);
                v00 += q0.x; v01 += q0.y; v10 += q1.x; v11 += q1.y;
            }
            if (EPI & EPI_SPLIT) {
                __nv_bfloat16 h0, l0, h1, l1;
                split_bf16(v00, h0, l0); split_bf16(v01, h1, l1);
                *(__nv_bfloat162*)(Chi + o0) = __nv_bfloat162(h0, h1);
                *(__nv_bfloat162*)(Clo + o0) = __nv_bfloat162(l0, l1);
                split_bf16(v10, h0, l0); split_bf16(v11, h1, l1);
                *(__nv_bfloat162*)(Chi + o1) = __nv_bfloat162(h0, h1);
                *(__nv_bfloat162*)(Clo + o1) = __nv_bfloat162(l0, l1);
            } else {
                *(float2*)(Cf + o0) = make_float2(v00, v01);
                *(float2*)(Cf + o1) = make_float2(v10, v11);
            }
        }
    }
}

// ---------------------------------------------------------------------------
// Weight transpose + bf16 split: W[K,N] fp32 -> Wt_hi/Wt_lo [N,K] bf16
// ---------------------------------------------------------------------------
__global__ void wtrans_kernel(const float* __restrict__ W,
                              __nv_bfloat16* __restrict__ hiT,
                              __nv_bfloat16* __restrict__ loT, int K, int N)
{
    const int idx = blockIdx.x * blockDim.x + threadIdx.x;
    if (idx >= K * N) return;
    const int k = idx / N, n = idx - k * N;
    __nv_bfloat16 h, l;
    split_bf16(W[idx], h, l);
    hiT[(size_t)n * K + k] = h;
    loT[(size_t)n * K + k] = l;
}

__global__ void cvt_split_kernel(const float* __restrict__ in,
                                 __nv_bfloat16* __restrict__ hi,
                                 __nv_bfloat16* __restrict__ lo, size_t n)
{
    const size_t idx = (size_t)blockIdx.x * blockDim.x + threadIdx.x;
    if (idx >= n) return;
    __nv_bfloat16 h, l;
    split_bf16(in[idx], h, l);
    hi[idx] = h; lo[idx] = l;
}

// ---------------------------------------------------------------------------
// Depthwise causal conv (k=4) + bias + SiLU -> xc fp32 + bf16 hi/lo
// ---------------------------------------------------------------------------
__global__ void conv_silu_kernel(const float* __restrict__ xz,
                                 const float* __restrict__ conv_w,
                                 const float* __restrict__ conv_b,
                                 float* __restrict__ xc,
                                 __nv_bfloat16* __restrict__ xchi,
                                 __nv_bfloat16* __restrict__ xclo)
{
    const int gid = blockIdx.x * blockDim.x + threadIdx.x;
    const int c   = gid & (HIDDEN - 1);
    const int row = gid >> 9;
    if (row >= ROWS) return;
    const int t = row & (SEQ - 1);

    float w0 = conv_w[c * 4 + 0], w1 = conv_w[c * 4 + 1];
    float w2 = conv_w[c * 4 + 2], w3 = conv_w[c * 4 + 3];

    float acc = conv_b[c];
    if (t >= 3) acc = fmaf(w0, xz[(size_t)(row - 3) * 1024 + c], acc);
    if (t >= 2) acc = fmaf(w1, xz[(size_t)(row - 2) * 1024 + c], acc);
    if (t >= 1) acc = fmaf(w2, xz[(size_t)(row - 1) * 1024 + c], acc);
    acc = fmaf(w3, xz[(size_t)row * 1024 + c], acc);

    const float v = siluf(acc);
    const size_t o = (size_t)row * HIDDEN + c;
    xc[o] = v;
    __nv_bfloat16 h, l;
    split_bf16(v, h, l);
    xchi[o] = h; xclo[o] = l;
}

// ---------------------------------------------------------------------------
// Scan
// ---------------------------------------------------------------------------
__device__ __forceinline__ void alpha_beta(float rec, float inp, float xcv,
                                           float spl, float& a, float& bp)
{
    float sr = sigmoidf_(rec);
    a = __expf(-spl * sr);
    float beta = sqrtf(1.0f - a * a + 1e-8f) * sigmoidf_(inp);
    bp = beta * xcv;
}

__global__ void scan_pass1_kernel(const float* __restrict__ gates,
                                  const float* __restrict__ xc,
                                  const float* __restrict__ Lambda,
                                  float* __restrict__ Pbuf,
                                  float* __restrict__ Sbuf)
{
    const int gid   = blockIdx.x * blockDim.x + threadIdx.x;
    const int c     = gid & (HIDDEN - 1);
    const int chunk = (gid >> 9) & (NCHUNK - 1);
    const int b     = gid >> 13;
    if (b >= BATCH) return;

    const float spl = log1pf(__expf(Lambda[c]));
    const int row0 = b * SEQ + chunk * CLEN;

    float P = 1.0f, S = 0.0f;
#pragma unroll 4
    for (int t = 0; t < CLEN; t++) {
        const size_t row = (size_t)(row0 + t);
        float rec = gates[row * 1024 + c];
        float inp = gates[row * 1024 + 512 + c];
        float xcv = xc[row * HIDDEN + c];
        float a, bp;
        alpha_beta(rec, inp, xcv, spl, a, bp);
        P *= a;
        S = fmaf(a, S, bp);
    }
    const size_t out = (size_t)(b * NCHUNK + chunk) * HIDDEN + c;
    Pbuf[out] = P;
    Sbuf[out] = S;
}

__global__ void scan_pass2_kernel(const float* __restrict__ Pbuf,
                                  const float* __restrict__ Sbuf,
                                  float* __restrict__ carry)
{
    const int gid = blockIdx.x * blockDim.x + threadIdx.x;
    const int c = gid & (HIDDEN - 1);
    const int b = gid >> 9;
    if (b >= BATCH) return;

    float h = 0.0f;
#pragma unroll
    for (int j = 0; j < NCHUNK; j++) {
        const size_t idx = (size_t)(b * NCHUNK + j) * HIDDEN + c;
        carry[idx] = h;
        h = fmaf(Pbuf[idx], h, Sbuf[idx]);
    }
}

__global__ void scan_pass3_kernel(const float* __restrict__ gates,
                                  const float* __restrict__ xc,
                                  const float* __restrict__ xz,
                                  const float* __restrict__ Lambda,
                                  const float* __restrict__ carry,
                                  __nv_bfloat16* __restrict__ ghi,
                                  __nv_bfloat16* __restrict__ glo)
{
    const int gid   = blockIdx.x * blockDim.x + threadIdx.x;
    const int c     = gid & (HIDDEN - 1);
    const int chunk = (gid >> 9) & (NCHUNK - 1);
    const int b     = gid >> 13;
    if (b >= BATCH) return;

    const float spl = log1pf(__expf(Lambda[c]));
    const int row0 = b * SEQ + chunk * CLEN;

    float h = carry[(size_t)(b * NCHUNK + chunk) * HIDDEN + c];
#pragma unroll 4
    for (int t = 0; t < CLEN; t++) {
        const size_t row = (size_t)(row0 + t);
        float rec = gates[row * 1024 + c];
        float inp = gates[row * 1024 + 512 + c];
        float xcv = xc[row * HIDDEN + c];
        float a, bp;
        alpha_beta(rec, inp, xcv, spl, a, bp);
        h = fmaf(a, h, bp);
        float z = xz[row * 1024 + 512 + c];
        const float g = h * siluf(z);
        __nv_bfloat16 gh, gl;
        split_bf16(g, gh, gl);
        ghi[row * HIDDEN + c] = gh;
        glo[row * HIDDEN + c] = gl;
    }
}

// ---------------------------------------------------------------------------
// LayerNorm over D=256. One warp per row. Optionally emit bf16 hi/lo split.
// ---------------------------------------------------------------------------
template <bool SPLIT>
__global__ void ln_kernel(const float* __restrict__ in,
                          const float* __restrict__ gamma,
                          const float* __restrict__ beta,
                          float* __restrict__ out,
                          __nv_bfloat16* __restrict__ ohi,
                          __nv_bfloat16* __restrict__ olo)
{
    const int warp = threadIdx.x >> 5;
    const int lane = threadIdx.x & 31;
    const int row = blockIdx.x * 8 + warp;

    const float* p = in + (size_t)row * DMODEL + lane * 8;
    float x[8];
    *(float4*)&x[0] = *(const float4*)(p);
    *(float4*)&x[4] = *(const float4*)(p + 4);

    float s = 0.0f;
#pragma unroll
    for (int i = 0; i < 8; i++) s += x[i];
#pragma unroll
    for (int o = 16; o > 0; o >>= 1) s += __shfl_xor_sync(0xFFFFFFFF, s, o);
    const float mean = s * (1.0f / DMODEL);

    float s2 = 0.0f;
#pragma unroll
    for (int i = 0; i < 8; i++) { float d = x[i] - mean; s2 = fmaf(d, d, s2); }
#pragma unroll
    for (int o = 16; o > 0; o >>= 1) s2 += __shfl_xor_sync(0xFFFFFFFF, s2, o);
    const float rs = rsqrtf(s2 * (1.0f / DMODEL) + 1e-12f);

    float gv[8], bv[8];
    *(float4*)&gv[0] = *(const float4*)(gamma + lane * 8);
    *(float4*)&gv[4] = *(const float4*)(gamma + lane * 8 + 4);
    *(float4*)&bv[0] = *(const float4*)(beta + lane * 8);
    *(float4*)&bv[4] = *(const float4*)(beta + lane * 8 + 4);

    float o_[8];
#pragma unroll
    for (int i = 0; i < 8; i++)
        o_[i] = fmaf((x[i] - mean) * rs, gv[i], bv[i]);

    const size_t base = (size_t)row * DMODEL + lane * 8;
    *(float4*)(out + base)     = *(float4*)&o_[0];
    *(float4*)(out + base + 4) = *(float4*)&o_[4];

    if (SPLIT) {
#pragma unroll
        for (int i = 0; i < 8; i += 2) {
            __nv_bfloat16 h0, l0, h1, l1;
            split_bf16(o_[i], h0, l0);
            split_bf16(o_[i + 1], h1, l1);
            *(__nv_bfloat162*)(ohi + base + i) = __nv_bfloat162(h0, h1);
            *(__nv_bfloat162*)(olo + base + i) = __nv_bfloat162(l0, l1);
        }
    }
}

// ---------------------------------------------------------------------------
// Launch
// ---------------------------------------------------------------------------
extern "C" void kernel_launch(void* const* d_in, const int* in_sizes, int n_in,
                              void* d_out, int out_size)
{
    const float* x      = (const float*)d_in[0];
    const float* w_in   = (const float*)d_in[1];
    const float* conv_w = (const float*)d_in[2];
    const float* conv_b = (const float*)d_in[3];
    const float* w_gts  = (const float*)d_in[4];
    const float* b_gts  = (const float*)d_in[5];
    const float* Lambda = (const float*)d_in[6];
    const float* w_out  = (const float*)d_in[7];
    const float* ln1_g  = (const float*)d_in[8];
    const float* ln1_b  = (const float*)d_in[9];
    const float* ffn_w1 = (const float*)d_in[10];
    const float* ffn_b1 = (const float*)d_in[11];
    const float* ffn_w2 = (const float*)d_in[12];
    const float* ffn_b2 = (const float*)d_in[13];
    const float* ln2_g  = (const float*)d_in[14];
    const float* ln2_b  = (const float*)d_in[15];
    float* out = (float*)d_out;

    float* fb = nullptr;
    __nv_bfloat16* bb = nullptr;
    cudaGetSymbolAddress((void**)&fb, g_fbuf);
    cudaGetSymbolAddress((void**)&bb, g_bbuf);

    float* xz    = fb + OFFF_XZ;
    float* xc    = fb + OFFF_XC;
    float* gates = fb + OFFF_GATES;
    float* hs    = fb + OFFF_HS;
    float* tbuf  = fb + OFFF_T;
    float* Pb    = fb + OFFF_P;
    float* Sb    = fb + OFFF_S;
    float* Cb    = fb + OFFF_CARRY;

    __nv_bfloat16 *xhi = bb + OFFB_XHI, *xlo = bb + OFFB_XLO;
    __nv_bfloat16 *xchi = bb + OFFB_XCHI, *xclo = bb + OFFB_XCLO;
    __nv_bfloat16 *ghi = bb + OFFB_GHI, *glo = bb + OFFB_GLO;
    __nv_bfloat16 *hshi = bb + OFFB_HSHI, *hslo = bb + OFFB_HSLO;
    __nv_bfloat16 *uhi = bb + OFFB_UHI, *ulo = bb + OFFB_ULO;
    __nv_bfloat16 *w1hi = bb + OFFB_W1HI, *w1lo = bb + OFFB_W1LO;
    __nv_bfloat16 *wghi = bb + OFFB_WGHI, *wglo = bb + OFFB_WGLO;
    __nv_bfloat16 *wohi = bb + OFFB_WOHI, *wolo = bb + OFFB_WOLO;
    __nv_bfloat16 *f1hi = bb + OFFB_F1HI, *f1lo = bb + OFFB_F1LO;
    __nv_bfloat16 *f2hi = bb + OFFB_F2HI, *f2lo = bb + OFFB_F2LO;

    cudaFuncSetAttribute(mma_gemm<0>,                               cudaFuncAttributeMaxDynamicSharedMemorySize, GEMM_DYN_SMEM);
    cudaFuncSetAttribute(mma_gemm<EPI_BIAS>,                        cudaFuncAttributeMaxDynamicSharedMemorySize, GEMM_DYN_SMEM);
    cudaFuncSetAttribute(mma_gemm<EPI_RESID>,                       cudaFuncAttributeMaxDynamicSharedMemorySize, GEMM_DYN_SMEM);
    cudaFuncSetAttribute(mma_gemm<EPI_BIAS | EPI_SILU | EPI_SPLIT>, cudaFuncAttributeMaxDynamicSharedMemorySize, GEMM_DYN_SMEM);
    cudaFuncSetAttribute(mma_gemm<EPI_BIAS | EPI_RESID>,            cudaFuncAttributeMaxDynamicSharedMemorySize, GEMM_DYN_SMEM);

    // 0) weight transpose + split ; x split
    wtrans_kernel<<<(256 * 1024 + 255) / 256, 256>>>(w_in,   w1hi, w1lo, 256,  1024);
    wtrans_kernel<<<(512 * 1024 + 255) / 256, 256>>>(w_gts,  wghi, wglo, 512,  1024);
    wtrans_kernel<<<(512 * 256  + 255) / 256, 256>>>(w_out,  wohi, wolo, 512,  256);
    wtrans_kernel<<<(256 * 1024 + 255) / 256, 256>>>(ffn_w1, f1hi, f1lo, 256,  1024);
    wtrans_kernel<<<(1024 * 256 + 255) / 256, 256>>>(ffn_w2, f2hi, f2lo, 1024, 256);
    cvt_split_kernel<<<(ROWS * 256) / 256, 256>>>(x, xhi, xlo, (size_t)ROWS * 256);

    const dim3 gW(1024 / 128, ROWS / 128);   // N=1024
    const dim3 gN(256 / 128,  ROWS / 128);   // N=256

    // 1) xz = x @ w_in
    mma_gemm<0><<<gW, 256, GEMM_DYN_SMEM>>>(xhi, xlo, w1hi, w1lo, nullptr, nullptr,
                                            xz, nullptr, nullptr, 1024, 256);
    // 2) xc = silu(conv(xh) + b)
    conv_silu_kernel<<<(ROWS * HIDDEN) / 256, 256>>>(xz, conv_w, conv_b, xc, xchi, xclo);
    // 3) gates = xc @ w_gates + b_gates
    mma_gemm<EPI_BIAS><<<gW, 256, GEMM_DYN_SMEM>>>(xchi, xclo, wghi, wglo, b_gts, nullptr,
                                                   gates, nullptr, nullptr, 1024, 512);
    // 4-6) chunked scan ; g = silu(z)*h (bf16 split)
    scan_pass1_kernel<<<(BATCH * NCHUNK * HIDDEN) / 256, 256>>>(gates, xc, Lambda, Pb, Sb);
    scan_pass2_kernel<<<(BATCH * HIDDEN) / 256, 256>>>(Pb, Sb, Cb);
    scan_pass3_kernel<<<(BATCH * NCHUNK * HIDDEN) / 256, 256>>>(gates, xc, xz, Lambda, Cb, ghi, glo);
    // 7) t = g @ w_out + x
    mma_gemm<EPI_RESID><<<gN, 256, GEMM_DYN_SMEM>>>(ghi, glo, wohi, wolo, nullptr, x,
                                                    tbuf, nullptr, nullptr, 256, 512);
    // 8) hs = LN1(t) (+ split)
    ln_kernel<true><<<ROWS / 8, 256>>>(tbuf, ln1_g, ln1_b, hs, hshi, hslo);
    // 9) u = silu(hs @ ffn_w1 + b1) -> bf16 split only
    mma_gemm<EPI_BIAS | EPI_SILU | EPI_SPLIT><<<gW, 256, GEMM_DYN_SMEM>>>(
        hshi, hslo, f1hi, f1lo, ffn_b1, nullptr, nullptr, uhi, ulo, 1024, 256);
    // 10) t = u @ ffn_w2 + b2 + hs
    mma_gemm<EPI_BIAS | EPI_RESID><<<gN, 256, GEMM_DYN_SMEM>>>(
        uhi, ulo, f2hi, f2lo, ffn_b2, hs, tbuf, nullptr, nullptr, 256, 1024);
    // 11) out = LN2(t)
    ln_kernel<false><<<ROWS / 8, 256>>>(tbuf, ln2_g, ln2_b, out, nullptr, nullptr);
}